// round 6
// baseline (speedup 1.0000x reference)
#include <cuda_runtime.h>
#include <math.h>

#define S_LEN 16
#define BSZ   64
#define NN    10000
#define LL    128
#define DMSG  129
#define DH    257
#define SCALE 0.08838834764831844f  // 1/sqrt(128)
#define TILE_N 50
#define NP    200                    // NN / TILE_N

// ---------------- scratch --------------------------------------------------------
__device__ float g_mem[NN * LL];
__device__ int   g_dirty[NN];
__device__ float g_newh[2 * BSZ * LL];
__device__ float g_ck[BSZ * DH];
__device__ float g_qbk[BSZ];
__device__ float g_memdot[NN];
__device__ float4 g_part[BSZ * NP];       // per (b,tile): {m, Z, V, pad}
__device__ float g_cv[DH];
__device__ float g_cvc;
__device__ float g_enc0[LL];

// ---------------- K0a ------------------------------------------------------------
__global__ void k_zero_mem() {
    int i = blockIdx.x * blockDim.x + threadIdx.x;
    if (i < NN * LL) g_mem[i] = 0.0f;
    if (i < NN) { g_memdot[i] = 0.0f; g_dirty[i] = 0; }
}

// ---------------- K0b ------------------------------------------------------------
__global__ void k_init(const float* __restrict__ Wv, const float* __restrict__ W_out,
                       const float* __restrict__ bv, const float* __restrict__ b_out,
                       const float* __restrict__ time_b) {
    int tid = threadIdx.x;
    if (tid < DH) {
        float a = 0.0f;
        const float* wr = Wv + tid * LL;
        for (int l = 0; l < LL; l++) a = fmaf(wr[l], W_out[l], a);
        g_cv[tid] = a;
    }
    if (tid < LL) g_enc0[tid] = cosf(time_b[tid]);
    if (tid == 280) {
        float a = 0.0f;
        for (int l = 0; l < LL; l++) a = fmaf(bv[l], W_out[l], a);
        g_cvc = a + b_out[0];
    }
}

// ---------------- no-op shim (aligns ncu -s 5 window onto k_scores) --------------
__global__ void k_noop() {
    if (blockIdx.x == 1) g_part[0].w = 0.0f;  // never true (grid=1); pure no-op
}

// ---------------- combine helper (online-softmax merge of NP partials) -----------
__device__ __forceinline__ void do_combine(float* __restrict__ out, int cs, int b) {
    __shared__ float s_m[12], s_z[12], s_v[12];
    int tid = threadIdx.x;            // 384
    int warp = tid >> 5, lane = tid & 31;
    float4 p = (tid < NP) ? g_part[b * NP + tid]
                          : make_float4(-1e30f, 0.0f, 0.0f, 0.0f);
    // max reduce
    float m = p.x;
#pragma unroll
    for (int o = 16; o; o >>= 1) m = fmaxf(m, __shfl_xor_sync(0xffffffffu, m, o));
    if (lane == 0) s_m[warp] = m;
    __syncthreads();
    if (tid < 12) {
        float v = s_m[tid];
        for (int o = 1; o < 12; o <<= 1) {
            float u = __shfl_xor_sync(0xfffu, v, o);
            if ((tid ^ o) < 12) v = fmaxf(v, u);
        }
        s_m[tid] = v;
    }
    __syncthreads();
    float M = s_m[0];
    // weighted sums
    float w = __expf(p.x - M);
    float Z = p.y * w, V = p.z * w;
#pragma unroll
    for (int o = 16; o; o >>= 1) {
        Z += __shfl_xor_sync(0xffffffffu, Z, o);
        V += __shfl_xor_sync(0xffffffffu, V, o);
    }
    if (lane == 0) { s_z[warp] = Z; s_v[warp] = V; }
    __syncthreads();
    if (tid == 0) {
        float z = 0.f, vv = 0.f;
        for (int i = 0; i < 12; i++) { z += s_z[i]; vv += s_v[i]; }
        out[cs * BSZ + b] = vv / z + g_cvc;
    }
}

// ---------------- K1: GRU (blocks 0..31, 4 cells each) + combine (32..95) --------
__global__ void __launch_bounds__(384) k_gru_comb(
        const float* __restrict__ x, const float* __restrict__ t,
        const int* __restrict__ src, const int* __restrict__ tgt,
        const float* __restrict__ time_w, const float* __restrict__ time_b,
        const float* __restrict__ W_ih, const float* __restrict__ W_hh,
        const float* __restrict__ b_ih, const float* __restrict__ b_hh,
        float* __restrict__ out, int s) {
    if (blockIdx.x >= 32) {           // combine role: finish step s-1
        if (s > 0) do_combine(out, s - 1, blockIdx.x - 32);
        return;
    }
    if (s >= S_LEN) return;           // final launch: combine only

    __shared__ float s_msg[4][160];
    __shared__ float s_h[4][LL];
    __shared__ float s_sum[2 * LL * 4];
    __shared__ float s_in[LL * 4];
    __shared__ float s_hn[LL * 4];
    __shared__ int   s_node[4];

    int tid = threadIdx.x;
    int warp = tid >> 5, lane = tid & 31;

    if (tid < 4) {
        int cell = blockIdx.x * 4 + tid;
        int b = cell & 63, is_t = cell >> 6;
        s_node[tid] = (is_t ? tgt : src)[s * BSZ + b];
    }
    __syncthreads();

#pragma unroll
    for (int c = 0; c < 4; c++) {
        int cell = blockIdx.x * 4 + c;
        int b = cell & 63;
        long base = ((long)(s * BSZ + b)) * NN + s_node[c];
        if (tid < LL) {
            s_h[c][tid] = g_mem[s_node[c] * LL + tid];
            float tv = t[base];
            s_msg[c][1 + tid] = cosf(fmaf(tv, time_w[tid], time_b[tid]));
        }
        if (tid == 128) s_msg[c][0] = x[base];
        if (tid >= 129 && tid < 160) s_msg[c][tid] = 0.0f;
    }
    __syncthreads();

    for (int i = 0; i < 32; i++) {
        int j = warp + 12 * i;
        const float* wi = W_ih + j * DMSG;
        const float* wh = W_hh + j * LL;
        float wreg[5], hreg[4];
#pragma unroll
        for (int ch = 0; ch < 5; ch++) {
            int d = ch * 32 + lane;
            wreg[ch] = (d < DMSG) ? __ldg(wi + d) : 0.0f;
        }
#pragma unroll
        for (int ch = 0; ch < 4; ch++) hreg[ch] = __ldg(wh + ch * 32 + lane);

        float ai[4] = {0, 0, 0, 0}, ah[4] = {0, 0, 0, 0};
#pragma unroll
        for (int c = 0; c < 4; c++) {
#pragma unroll
            for (int ch = 0; ch < 5; ch++) ai[c] = fmaf(wreg[ch], s_msg[c][ch * 32 + lane], ai[c]);
#pragma unroll
            for (int ch = 0; ch < 4; ch++) ah[c] = fmaf(hreg[ch], s_h[c][ch * 32 + lane], ah[c]);
        }

        if (j < 2 * LL) {
            float v[4];
#pragma unroll
            for (int c = 0; c < 4; c++) {
                v[c] = ai[c] + ah[c];
#pragma unroll
                for (int o = 16; o; o >>= 1) v[c] += __shfl_xor_sync(0xffffffffu, v[c], o);
            }
            if (lane == 0) {
                float bb = b_ih[j] + b_hh[j];
#pragma unroll
                for (int c = 0; c < 4; c++) s_sum[j * 4 + c] = v[c] + bb;
            }
        } else {
#pragma unroll
            for (int c = 0; c < 4; c++) {
#pragma unroll
                for (int o = 16; o; o >>= 1) {
                    ai[c] += __shfl_xor_sync(0xffffffffu, ai[c], o);
                    ah[c] += __shfl_xor_sync(0xffffffffu, ah[c], o);
                }
            }
            if (lane == 0) {
                float bi = b_ih[j], bh = b_hh[j];
                int jj = j - 2 * LL;
#pragma unroll
                for (int c = 0; c < 4; c++) {
                    s_in[jj * 4 + c] = ai[c] + bi;
                    s_hn[jj * 4 + c] = ah[c] + bh;
                }
            }
        }
    }
    __syncthreads();

    if (tid < LL) {
#pragma unroll
        for (int c = 0; c < 4; c++) {
            int cell = blockIdx.x * 4 + c;
            float r = 1.0f / (1.0f + __expf(-s_sum[tid * 4 + c]));
            float z = 1.0f / (1.0f + __expf(-s_sum[(LL + tid) * 4 + c]));
            float nn = tanhf(fmaf(r, s_hn[tid * 4 + c], s_in[tid * 4 + c]));
            g_newh[cell * LL + tid] = fmaf(z, s_h[c][tid] - nn, nn);
        }
    }
}

// ---------------- K2: update = scatter (blocks 0..127) + qck (128..191) ----------
__global__ void __launch_bounds__(256) k_update(
        const float* __restrict__ x, const int* __restrict__ src,
        const int* __restrict__ tgt,
        const float* __restrict__ Wq, const float* __restrict__ bq,
        const float* __restrict__ Wk, const float* __restrict__ bk, int s) {
    __shared__ int s_nodes[2 * BSZ];
    int tid = threadIdx.x;

    if (tid < 128)
        s_nodes[tid] = (tid < BSZ) ? src[s * BSZ + tid] : tgt[s * BSZ + (tid - BSZ)];
    __syncthreads();

    if (blockIdx.x < 128) {
        // ---- scatter role ----
        __shared__ float s_red[4];
        int c = blockIdx.x;
        int my = s_nodes[c];
        bool loser = (tid < 128) && (tid > c) && (s_nodes[tid] == my);
        if (__syncthreads_or(loser)) return;
        if (tid < 128) {
            float v = g_newh[c * LL + tid];
            g_mem[my * LL + tid] = v;
            float a = v * g_cv[1 + tid];
#pragma unroll
            for (int o = 16; o; o >>= 1) a += __shfl_xor_sync(0xffffffffu, a, o);
            if ((tid & 31) == 0) s_red[tid >> 5] = a;
        }
        __syncthreads();
        if (tid == 0) {
            g_memdot[my] = s_red[0] + s_red[1] + s_red[2] + s_red[3];
            g_dirty[my] = 1;
        }
        return;
    }

    // ---- qck role ----
    __shared__ float s_th[DH];
    __shared__ float s_qp[2][LL];
    __shared__ float s_q[LL];
    __shared__ int s_win;
    int b = blockIdx.x - 128;
    int warp = tid >> 5, lane = tid & 31;
    int mynode = s_nodes[BSZ + b];
    if (tid == 0) s_win = BSZ + b;   // cell 64+b always writes this node
    __syncthreads();
    if (tid < 128 && s_nodes[tid] == mynode) atomicMax(&s_win, tid);
    __syncthreads();
    int cwin = s_win;

    if (tid == 0) s_th[0] = x[((long)(s * BSZ + b)) * NN + mynode];
    if (tid < LL) {
        s_th[1 + tid] = g_newh[cwin * LL + tid];   // post-update memory of tgt node
        s_th[1 + LL + tid] = g_enc0[tid];
    }
    __syncthreads();
    {
        int l = tid & 127, half = tid >> 7;
        int d0 = half * 128, d1 = half ? DH : 128;
        float a0 = 0.f, a1 = 0.f, a2 = 0.f, a3 = 0.f;
        int d = d0;
        for (; d + 3 < d1; d += 4) {
            a0 = fmaf(s_th[d],     __ldg(Wq + (d    ) * LL + l), a0);
            a1 = fmaf(s_th[d + 1], __ldg(Wq + (d + 1) * LL + l), a1);
            a2 = fmaf(s_th[d + 2], __ldg(Wq + (d + 2) * LL + l), a2);
            a3 = fmaf(s_th[d + 3], __ldg(Wq + (d + 3) * LL + l), a3);
        }
        for (; d < d1; d++) a0 = fmaf(s_th[d], __ldg(Wq + d * LL + l), a0);
        s_qp[half][l] = (a0 + a1) + (a2 + a3);
    }
    __syncthreads();
    if (tid < LL) s_q[tid] = s_qp[0][tid] + s_qp[1][tid] + bq[tid];
    __syncthreads();

    for (int d = warp; d < DH; d += 8) {
        float a = 0.0f;
        const float* wr = Wk + d * LL;
#pragma unroll
        for (int ch = 0; ch < 4; ch++) a = fmaf(__ldg(wr + ch * 32 + lane), s_q[ch * 32 + lane], a);
#pragma unroll
        for (int o = 16; o; o >>= 1) a += __shfl_xor_sync(0xffffffffu, a, o);
        if (lane == 0) g_ck[b * DH + d] = SCALE * a;
    }
    if (tid == 0) {
        float a = 0.0f;
        for (int l = 0; l < LL; l++) a = fmaf(s_q[l], bk[l], a);
        g_qbk[b] = SCALE * a;
    }
}

// ---------------- K3: scores + online softmax partials ---------------------------
__global__ void __launch_bounds__(256) k_scores(
        const float* __restrict__ x, const float* __restrict__ t,
        const int* __restrict__ mask,
        const float* __restrict__ time_w, const float* __restrict__ time_b, int s) {
    int tid = threadIdx.x;
    int warp = tid >> 5, lane = tid & 31;
    int n0 = blockIdx.x * TILE_N;
    int b = blockIdx.y * 8 + warp;
    long base = ((long)(s * BSZ + b)) * NN;

    // lane-staged row data
    int nA = n0 + lane;
    int nB = n0 + 32 + ((lane < 18) ? lane : 17);
    float tA = __ldg(t + base + nA),    tB = __ldg(t + base + nB);
    int   mA = __ldg(mask + base + nA), mB = __ldg(mask + base + nB);
    float xA = __ldg(x + base + nA),    xB = __ldg(x + base + nB);
    int   dA = g_dirty[nA],             dB = g_dirty[nB];
    float mdA = g_memdot[nA],           mdB = g_memdot[nB];

    float tw[4], tc[4], ckd[4], ckm[4], cvd[4];
#pragma unroll
    for (int j = 0; j < 4; j++) {
        int l = j * 32 + lane;
        tw[j]  = time_w[l];
        tc[j]  = time_b[l];
        ckd[j] = g_ck[b * DH + 1 + LL + l];
        ckm[j] = g_ck[b * DH + 1 + l];
        cvd[j] = g_cv[1 + LL + l];
    }
    float ck0 = g_ck[b * DH];
    float qbk = g_qbk[b];
    float cv0 = g_cv[0];

    float m = -1e30f, Z = 0.0f, V1 = 0.0f;
    float acc0 = 0.f, acc1 = 0.f, acc2 = 0.f, acc3 = 0.f;

#pragma unroll 2
    for (int r = 0; r < TILE_N; r++) {
        bool grpA = (r < 32);
        int idx = grpA ? r : (r - 32);
        int mr = __shfl_sync(0xffffffffu, grpA ? mA : mB, idx);
        if (!mr) continue;
        float tv = __shfl_sync(0xffffffffu, grpA ? tA : tB, idx);
        int dirty = __shfl_sync(0xffffffffu, grpA ? dA : dB, idx);

        float cw0 = __cosf(fmaf(tv, tw[0], tc[0]));
        float cw1 = __cosf(fmaf(tv, tw[1], tc[1]));
        float cw2 = __cosf(fmaf(tv, tw[2], tc[2]));
        float cw3 = __cosf(fmaf(tv, tw[3], tc[3]));
        float sp = ckd[0] * cw0;
        sp = fmaf(ckd[1], cw1, sp);
        sp = fmaf(ckd[2], cw2, sp);
        sp = fmaf(ckd[3], cw3, sp);
        if (dirty) {
            const float* mr_ = g_mem + (long)(n0 + r) * LL;
            sp = fmaf(ckm[0], __ldg(mr_ + lane), sp);
            sp = fmaf(ckm[1], __ldg(mr_ + 32 + lane), sp);
            sp = fmaf(ckm[2], __ldg(mr_ + 64 + lane), sp);
            sp = fmaf(ckm[3], __ldg(mr_ + 96 + lane), sp);
        }
#pragma unroll
        for (int o = 16; o; o >>= 1) sp += __shfl_xor_sync(0xffffffffu, sp, o);

        float xr  = __shfl_sync(0xffffffffu, grpA ? xA : xB, idx);
        float mdr = __shfl_sync(0xffffffffu, grpA ? mdA : mdB, idx);
        float sc = fmaf(ck0, xr, sp) + qbk;
        float val = fmaf(cv0, xr, mdr);

        if (sc > m) {
            float sca = __expf(m - sc);
            Z = fmaf(Z, sca, 1.0f);
            V1 = fmaf(V1, sca, val);
            acc0 = fmaf(acc0, sca, cw0);
            acc1 = fmaf(acc1, sca, cw1);
            acc2 = fmaf(acc2, sca, cw2);
            acc3 = fmaf(acc3, sca, cw3);
            m = sc;
        } else {
            float e = __expf(sc - m);
            Z += e;
            V1 = fmaf(e, val, V1);
            acc0 = fmaf(e, cw0, acc0);
            acc1 = fmaf(e, cw1, acc1);
            acc2 = fmaf(e, cw2, acc2);
            acc3 = fmaf(e, cw3, acc3);
        }
    }

    // contract dt-value: Vdt = sum_l cvd[l] * acc[l]
    float w = cvd[0] * acc0;
    w = fmaf(cvd[1], acc1, w);
    w = fmaf(cvd[2], acc2, w);
    w = fmaf(cvd[3], acc3, w);
#pragma unroll
    for (int o = 16; o; o >>= 1) w += __shfl_xor_sync(0xffffffffu, w, o);

    if (lane == 0)
        g_part[b * NP + blockIdx.x] = make_float4(m, Z, V1 + w, 0.0f);
}

// ---------------- host -----------------------------------------------------------
extern "C" void kernel_launch(void* const* d_in, const int* in_sizes, int n_in,
                              void* d_out, int out_size) {
    const float* x       = (const float*)d_in[0];
    const float* t       = (const float*)d_in[1];
    const int*   src     = (const int*)d_in[2];
    const int*   tgt     = (const int*)d_in[3];
    const int*   mask    = (const int*)d_in[4];
    const float* time_w  = (const float*)d_in[5];
    const float* time_b  = (const float*)d_in[6];
    const float* W_ih    = (const float*)d_in[7];
    const float* W_hh    = (const float*)d_in[8];
    const float* b_ih    = (const float*)d_in[9];
    const float* b_hh    = (const float*)d_in[10];
    const float* Wq      = (const float*)d_in[11];
    const float* bq      = (const float*)d_in[12];
    const float* Wk      = (const float*)d_in[13];
    const float* bk      = (const float*)d_in[14];
    const float* Wv      = (const float*)d_in[15];
    const float* bv      = (const float*)d_in[16];
    const float* W_out   = (const float*)d_in[17];
    const float* b_out   = (const float*)d_in[18];
    float* out = (float*)d_out;

    k_zero_mem<<<(NN * LL + 255) / 256, 256>>>();
    k_init<<<1, 288>>>(Wv, W_out, bv, b_out, time_b);
    k_noop<<<1, 32>>>();   // aligns ncu -s 5 -c 1 onto step-0 k_scores

    for (int s = 0; s < S_LEN; s++) {
        k_gru_comb<<<96, 384>>>(x, t, src, tgt, time_w, time_b,
                                W_ih, W_hh, b_ih, b_hh, out, s);
        k_update<<<192, 256>>>(x, src, tgt, Wq, bq, Wk, bk, s);
        k_scores<<<dim3(NP, 8), 256>>>(x, t, mask, time_w, time_b, s);
    }
    // final combine for step 15 (gru role is a no-op at s == S_LEN)
    k_gru_comb<<<96, 384>>>(x, t, src, tgt, time_w, time_b,
                            W_ih, W_hh, b_ih, b_hh, out, S_LEN);
}